// round 1
// baseline (speedup 1.0000x reference)
#include <cuda_runtime.h>
#include <math.h>

// Problem constants (shapes are fixed by the dataset)
#define N_TOT 8192
#define D 128
#define TEMP_INV (1.0f/0.07f)
#define BM 128
#define BN 64
#define NCHUNK 16
#define JCHUNK (N_TOT/NCHUNK)   /* 512 */
#define SUBT (JCHUNK/BN)        /* 8   */
#define NBLK_M (N_TOT/BM)       /* 64  */
#define FIN_BLOCKS 32

// Scratch (no allocations allowed -> __device__ globals)
__device__ float g_G[2][D];
__device__ int   g_C[2];
__device__ int   g_valid[N_TOT];
__device__ float g_pm[NCHUNK][N_TOT];
__device__ float g_ps[NCHUNK][N_TOT];
__device__ float g_bsum[FIN_BLOCKS];
__device__ int   g_is64;

// ---------------------------------------------------------------------------
// Kernel 0: zero class sums/counts + detect whether labels are int64 or int32.
// Labels are {0,1}; if stored as little-endian int64, every odd 32-bit word is 0.
// ---------------------------------------------------------------------------
__global__ void init_detect_k(const int* __restrict__ lw) {
    int t = threadIdx.x;
    if (t < 2 * D) ((float*)g_G)[t] = 0.0f;
    if (t < 2)     g_C[t] = 0;

    int local = 0;
    for (int i = 1 + 2 * t; i < N_TOT; i += 2 * 256) local |= lw[i];
    __shared__ int anynz;
    if (t == 0) anynz = 0;
    __syncthreads();
    if (local) atomicOr(&anynz, 1);
    __syncthreads();
    if (t == 0) g_is64 = anynz ? 0 : 1;
}

// ---------------------------------------------------------------------------
// Kernel 1: valid mask + per-class feature sums G[c][k] and counts C[c].
// Block = 128 threads (one per k), each block covers 128 rows.
// ---------------------------------------------------------------------------
__global__ void prep_k(const float* __restrict__ f, const int* __restrict__ lw) {
    int k  = threadIdx.x;             // 0..127
    int r0 = blockIdx.x * 128;
    int is64 = g_is64;
    float a0 = 0.f, a1 = 0.f;
    int c0 = 0, c1 = 0;
    for (int r = 0; r < 128; r++) {
        int row = r0 + r;
        float v = f[(size_t)row * D + k];
        int nz = __syncthreads_or(v != 0.0f);
        if (k == 0) g_valid[row] = nz;
        if (nz) {
            int lab = is64 ? lw[2 * row] : lw[row];
            if (lab == 0) a0 += v; else a1 += v;
            if (k == 0) { if (lab == 0) c0++; else c1++; }
        }
    }
    atomicAdd(&g_G[0][k], a0);
    atomicAdd(&g_G[1][k], a1);
    if (k == 0) { atomicAdd(&g_C[0], c0); atomicAdd(&g_C[1], c1); }
}

// ---------------------------------------------------------------------------
// Kernel 2: the big one. Tiled f * f^T with fused online logsumexp.
// Grid (64 anchor tiles, 16 J-chunks). Block 256 threads.
// SMEM: As[k][m] 128x128, Bs[k][n] 128x64 (both k-major, conflict-free inner LDS),
// Bv[64] valid flags. 96.25 KB dynamic -> 2 blocks/SM.
// Each thread: 8 anchors x 4 cols micro-tile; online (max, sumexp) per anchor row;
// shfl-combined across the 16 lanes sharing a row; partial written per chunk.
// ---------------------------------------------------------------------------
__global__ void __launch_bounds__(256) lse_k(const float* __restrict__ f) {
    extern __shared__ float sm[];
    float* As = sm;                     // [D][BM]
    float* Bs = sm + D * BM;            // [D][BN]
    int*   Bv = (int*)(Bs + D * BN);    // [BN]

    const int tid = threadIdx.x;
    const int tx  = tid & 15;           // column group
    const int ty  = tid >> 4;           // row group
    const int gm0 = blockIdx.x * BM;
    const int j0  = blockIdx.y * JCHUNK;

    // Fill A transposed (STS conflict-free: lanes vary m)
    #pragma unroll
    for (int it = 0; it < 16; ++it) {
        int idx = tid + it * 256;
        int m = idx & 127, kq = idx >> 7;
        float4 v = *(const float4*)(f + (size_t)(gm0 + m) * D + kq * 4);
        As[(kq * 4 + 0) * BM + m] = v.x;
        As[(kq * 4 + 1) * BM + m] = v.y;
        As[(kq * 4 + 2) * BM + m] = v.z;
        As[(kq * 4 + 3) * BM + m] = v.w;
    }

    float mrun[8], srun[8];
    #pragma unroll
    for (int r = 0; r < 8; r++) { mrun[r] = -INFINITY; srun[r] = 0.f; }

    for (int jt = 0; jt < SUBT; ++jt) {
        int gj0 = j0 + jt * BN;
        __syncthreads();   // prev compute done reading Bs (and A fill visible on jt==0)
        #pragma unroll
        for (int it = 0; it < 8; ++it) {
            int idx = tid + it * 256;
            int n = idx & 63, kq = idx >> 6;
            float4 v = *(const float4*)(f + (size_t)(gj0 + n) * D + kq * 4);
            Bs[(kq * 4 + 0) * BN + n] = v.x;
            Bs[(kq * 4 + 1) * BN + n] = v.y;
            Bs[(kq * 4 + 2) * BN + n] = v.z;
            Bs[(kq * 4 + 3) * BN + n] = v.w;
        }
        if (tid < BN) Bv[tid] = g_valid[gj0 + tid];
        __syncthreads();

        float acc[8][4];
        #pragma unroll
        for (int r = 0; r < 8; r++)
            #pragma unroll
            for (int c = 0; c < 4; c++) acc[r][c] = 0.f;

        #pragma unroll 8
        for (int k = 0; k < D; k++) {
            float4 a0 = *(const float4*)(As + k * BM + ty * 8);
            float4 a1 = *(const float4*)(As + k * BM + ty * 8 + 4);
            float4 b  = *(const float4*)(Bs + k * BN + tx * 4);
            float av[8] = {a0.x, a0.y, a0.z, a0.w, a1.x, a1.y, a1.z, a1.w};
            float bv[4] = {b.x, b.y, b.z, b.w};
            #pragma unroll
            for (int r = 0; r < 8; r++)
                #pragma unroll
                for (int c = 0; c < 4; c++)
                    acc[r][c] = fmaf(av[r], bv[c], acc[r][c]);
        }

        int ok0 = Bv[tx * 4 + 0], ok1 = Bv[tx * 4 + 1];
        int ok2 = Bv[tx * 4 + 2], ok3 = Bv[tx * 4 + 3];
        #pragma unroll
        for (int r = 0; r < 8; r++) {
            float v0 = acc[r][0] * TEMP_INV, v1 = acc[r][1] * TEMP_INV;
            float v2 = acc[r][2] * TEMP_INV, v3 = acc[r][3] * TEMP_INV;
            float tmax = -INFINITY;
            if (ok0) tmax = fmaxf(tmax, v0);
            if (ok1) tmax = fmaxf(tmax, v1);
            if (ok2) tmax = fmaxf(tmax, v2);
            if (ok3) tmax = fmaxf(tmax, v3);
            if (tmax > mrun[r]) {            // __expf(-inf) == 0, safe when mrun=-inf
                srun[r] *= __expf(mrun[r] - tmax);
                mrun[r] = tmax;
            }
            float s = srun[r];
            if (ok0) s += __expf(v0 - mrun[r]);
            if (ok1) s += __expf(v1 - mrun[r]);
            if (ok2) s += __expf(v2 - mrun[r]);
            if (ok3) s += __expf(v3 - mrun[r]);
            srun[r] = s;
        }
    }

    // Combine (m, s) across the 16 lanes (tx) owning the same anchor rows.
    #pragma unroll
    for (int r = 0; r < 8; r++) {
        float m = mrun[r], s = srun[r];
        #pragma unroll
        for (int off = 8; off > 0; off >>= 1) {
            float m2 = __shfl_xor_sync(0xffffffffu, m, off, 16);
            float s2 = __shfl_xor_sync(0xffffffffu, s, off, 16);
            float M = fmaxf(m, m2);
            float sn;
            if (M == -INFINITY) sn = 0.f;
            else sn = ((m  == -INFINITY) ? 0.f : s  * __expf(m  - M))
                    + ((m2 == -INFINITY) ? 0.f : s2 * __expf(m2 - M));
            m = M; s = sn;
        }
        if (tx == 0) {
            int anchor = gm0 + ty * 8 + r;
            g_pm[blockIdx.y][anchor] = m;
            g_ps[blockIdx.y][anchor] = s;
        }
    }
}

// ---------------------------------------------------------------------------
// Kernel 3: per-anchor finalize. Combine NCHUNK partials -> lse; dot with G;
// term_i = (C[lab]*lse_i - dot(f_i,G[lab])/T) / 128 (valid anchors only).
// Deterministic block tree-sum -> g_bsum.
// ---------------------------------------------------------------------------
__global__ void fin_k(const float* __restrict__ f, const int* __restrict__ lw) {
    __shared__ float Gs[2 * D];
    __shared__ float red[256];
    int t = threadIdx.x;
    Gs[t] = ((const float*)g_G)[t];
    __syncthreads();

    int i = blockIdx.x * 256 + t;
    float M = -INFINITY, S = 0.f;
    #pragma unroll
    for (int c = 0; c < NCHUNK; c++) {
        float m2 = g_pm[c][i], s2 = g_ps[c][i];
        float Mn = fmaxf(M, m2);
        float Sn;
        if (Mn == -INFINITY) Sn = 0.f;
        else Sn = ((M  == -INFINITY) ? 0.f : S  * __expf(M  - Mn))
                + ((m2 == -INFINITY) ? 0.f : s2 * __expf(m2 - Mn));
        M = Mn; S = Sn;
    }

    float term = 0.f;
    if (g_valid[i]) {
        float lse = M + logf(S);
        int lab = g_is64 ? lw[2 * i] : lw[i];
        const float4* fr = (const float4*)(f + (size_t)i * D);
        const float4* gr = (const float4*)(Gs + lab * D);
        float dot = 0.f;
        #pragma unroll
        for (int k = 0; k < D / 4; k++) {
            float4 a = fr[k]; float4 g = gr[k];
            dot = fmaf(a.x, g.x, dot); dot = fmaf(a.y, g.y, dot);
            dot = fmaf(a.z, g.z, dot); dot = fmaf(a.w, g.w, dot);
        }
        float cnt = (float)g_C[lab];
        term = (cnt * lse - dot * TEMP_INV) * (1.0f / 128.0f);
    }
    red[t] = term;
    __syncthreads();
    for (int st = 128; st > 0; st >>= 1) {
        if (t < st) red[t] += red[t + st];
        __syncthreads();
    }
    if (t == 0) g_bsum[blockIdx.x] = red[0];
}

// Kernel 4: deterministic final sum -> loss = sum/b, b = 256.
__global__ void fin2_k(float* out) {
    if (threadIdx.x == 0) {
        float s = 0.f;
        for (int i = 0; i < FIN_BLOCKS; i++) s += g_bsum[i];
        out[0] = s * (1.0f / 256.0f);
    }
}

// ---------------------------------------------------------------------------
extern "C" void kernel_launch(void* const* d_in, const int* in_sizes, int n_in,
                              void* d_out, int out_size) {
    const float* f  = (const float*)d_in[0];
    const int*   lw = (const int*)d_in[1];   // labels viewed as 32-bit words
    float* out = (float*)d_out;

    const int SMEM_BYTES = (D * BM + D * BN + BN) * 4;  // 98560 B
    cudaFuncSetAttribute(lse_k, cudaFuncAttributeMaxDynamicSharedMemorySize, SMEM_BYTES);

    init_detect_k<<<1, 256>>>(lw);
    prep_k<<<NBLK_M, 128>>>(f, lw);
    lse_k<<<dim3(NBLK_M, NCHUNK), 256, SMEM_BYTES>>>(f);
    fin_k<<<FIN_BLOCKS, 256>>>(f, lw);
    fin2_k<<<1, 32>>>(out);
}